// round 7
// baseline (speedup 1.0000x reference)
#include <cuda_runtime.h>
#include <math.h>
#include <stdint.h>

// Problem constants
#define DD   1024          // model dim
#define HH   2048          // expert hidden
#define EE   8             // experts
#define TT   8192          // tokens (B*L = 4*2048)
#define KTOP 2
#define NMOE (TT * KTOP)   // 16384 moe assignments
#define NROWS (NMOE + TT)  // 24576 total grouped rows (moe + shared)

// ---------------------------------------------------------------------------
// Scratch (static __device__ globals: allocation-free per harness rules)
// ---------------------------------------------------------------------------
__device__ float g_hidden[(size_t)NROWS * HH];   // ~192 MiB
__device__ float g_y[(size_t)NMOE * DD];         // ~64 MiB
__device__ int   g_count[EE];
__device__ int   g_offs[EE + 1];
__device__ int   g_tok[EE * TT];                 // per-expert token lists
__device__ int   g_asg_e[NMOE];
__device__ int   g_asg_pos[NMOE];
__device__ float g_asg_w[NMOE];

// ---------------------------------------------------------------------------
// Helpers
// ---------------------------------------------------------------------------
__device__ __forceinline__ uint32_t f2tf(float f) {
    uint32_t r;
    asm("cvt.rna.tf32.f32 %0, %1;" : "=r"(r) : "f"(f));
    return r;
}

__device__ __forceinline__ void mma8(float c[4], const uint32_t a[4], const uint32_t b[2]) {
    asm volatile(
        "mma.sync.aligned.m16n8k8.row.col.f32.tf32.tf32.f32 "
        "{%0,%1,%2,%3},{%4,%5,%6,%7},{%8,%9},{%0,%1,%2,%3};\n"
        : "+f"(c[0]), "+f"(c[1]), "+f"(c[2]), "+f"(c[3])
        : "r"(a[0]), "r"(a[1]), "r"(a[2]), "r"(a[3]), "r"(b[0]), "r"(b[1]));
}

__device__ __forceinline__ void cp16(uint32_t smem_dst, const void* gmem_src, int src_size) {
    asm volatile("cp.async.ca.shared.global [%0], [%1], 16, %2;"
                 :: "r"(smem_dst), "l"(gmem_src), "r"(src_size));
}
__device__ __forceinline__ void cp_commit() { asm volatile("cp.async.commit_group;"); }
__device__ __forceinline__ void cp_wait2()  { asm volatile("cp.async.wait_group 2;" ::: "memory"); }

// convert 4 words at smem location in place (own data, post-wait)
__device__ __forceinline__ void cvt4(uint32_t* p) {
    uint4 v = *reinterpret_cast<uint4*>(p);
    v.x = f2tf(__uint_as_float(v.x));
    v.y = f2tf(__uint_as_float(v.y));
    v.z = f2tf(__uint_as_float(v.z));
    v.w = f2tf(__uint_as_float(v.w));
    *reinterpret_cast<uint4*>(p) = v;
}

__device__ __forceinline__ float silu_f(float v) {
    return v / (1.0f + __expf(-v));
}

// ---------------------------------------------------------------------------
// K0: zero counts (fresh every graph replay)
// ---------------------------------------------------------------------------
__global__ void zero_counts_kernel() {
    if (threadIdx.x < EE) g_count[threadIdx.x] = 0;
}

// ---------------------------------------------------------------------------
// K1: router — logits, top-2, softmax weights, build expert token lists
// ---------------------------------------------------------------------------
__global__ void router_kernel(const float* __restrict__ x,
                              const float* __restrict__ rw,
                              const float* __restrict__ bias) {
    int warp = threadIdx.x >> 5;
    int lane = threadIdx.x & 31;
    int t = blockIdx.x * 8 + warp;

    const float* xr = x + (size_t)t * DD;
    float xv[32];
#pragma unroll
    for (int i = 0; i < 32; i++) xv[i] = xr[lane + (i << 5)];

    float logit[EE];
#pragma unroll
    for (int e = 0; e < EE; e++) {
        const float* we = rw + e * DD;
        float acc = 0.0f;
#pragma unroll
        for (int i = 0; i < 32; i++) acc += xv[i] * we[lane + (i << 5)];
#pragma unroll
        for (int o = 16; o > 0; o >>= 1) acc += __shfl_xor_sync(0xffffffffu, acc, o);
        logit[e] = acc + bias[e];
    }

    if (lane == 0) {
        int e0 = 0;
#pragma unroll
        for (int e = 1; e < EE; e++) if (logit[e] > logit[e0]) e0 = e;
        int e1 = -1;
#pragma unroll
        for (int e = 0; e < EE; e++) {
            if (e == e0) continue;
            if (e1 < 0 || logit[e] > logit[e1]) e1 = e;
        }
        float l0 = logit[e0], l1 = logit[e1];
        float p1 = expf(l1 - l0);              // <= 1
        float inv = 1.0f / (1.0f + p1);
        float w0 = inv, w1 = p1 * inv;

        int pos0 = atomicAdd(&g_count[e0], 1);
        int pos1 = atomicAdd(&g_count[e1], 1);
        g_tok[e0 * TT + pos0] = t;
        g_tok[e1 * TT + pos1] = t;
        g_asg_e[2 * t]     = e0; g_asg_pos[2 * t]     = pos0; g_asg_w[2 * t]     = w0;
        g_asg_e[2 * t + 1] = e1; g_asg_pos[2 * t + 1] = pos1; g_asg_w[2 * t + 1] = w1;
    }
}

// ---------------------------------------------------------------------------
// K2: prefix offsets
// ---------------------------------------------------------------------------
__global__ void offsets_kernel() {
    if (threadIdx.x == 0 && blockIdx.x == 0) {
        int a = 0;
        for (int e = 0; e < EE; e++) { g_offs[e] = a; a += g_count[e]; }
        g_offs[EE] = a;
    }
}

// ---------------------------------------------------------------------------
// K3: grouped GEMM1 (dual): hidden = silu(X W1) * (X W3), gathered rows.
// grid (64, HH/64, 9), block 256. Tile 128x64 dual. 4-stage cp.async ring,
// prefetch distance 2, producer-side tf32 conversion, 1 barrier per K-tile.
// ---------------------------------------------------------------------------
#define A_OFF   0
#define A_WORDS (128 * 20)                 // stride 20, conflict-free
#define B1_OFF  A_WORDS                    // 2560
#define B1_WORDS (16 * 72)                 // stride 72, conflict-free
#define B3_OFF  (B1_OFF + B1_WORDS)        // 3712
#define STG1_WORDS (A_WORDS + 2 * B1_WORDS)   // 4864
#define STG1_BYTES (STG1_WORDS * 4)           // 19456
#define SMEM1_BYTES (4 * STG1_BYTES)          // 77824

__global__ __launch_bounds__(256, 2)
void gemm1_kernel(const float* __restrict__ x,
                  const float* __restrict__ w1, const float* __restrict__ w3,
                  const float* __restrict__ sw1, const float* __restrict__ sw3) {
    extern __shared__ uint32_t smemw[];

    int g = blockIdx.z;
    int M, rowbase;
    const int* toks;
    const float *W1, *W3;
    if (g < EE) {
        M = g_count[g]; rowbase = g_offs[g]; toks = g_tok + g * TT;
        W1 = w1 + (size_t)g * DD * HH; W3 = w3 + (size_t)g * DD * HH;
    } else {
        M = TT; rowbase = NMOE; toks = nullptr;
        W1 = sw1; W3 = sw3;
    }
    int bm0 = blockIdx.x * 128;
    if (bm0 >= M) return;
    int n0 = blockIdx.y * 64;

    int tid  = threadIdx.x;
    int lane = tid & 31, wid = tid >> 5;
    int wm = wid & 3, wn = wid >> 2;       // 4x2 warps -> 32x32 per warp
    int t4 = lane & 3, t8 = lane >> 2;

    float accG[2][4][4] = {}, accU[2][4][4] = {};

    // A slots: 2 x 16B per thread (128 rows x 4 chunks)
    const float* arow[2];
    int asz[2], aoff[2];
#pragma unroll
    for (int i = 0; i < 2; i++) {
        int s = tid + i * 256;
        int m = s >> 2;
        int kq = (s & 3) << 2;
        int gm = bm0 + m;
        if (gm < M) {
            int tr = toks ? toks[gm] : gm;
            arow[i] = x + (size_t)tr * DD + kq;
            asz[i] = 16;
        } else {
            arow[i] = x;
            asz[i] = 0;
        }
        aoff[i] = A_OFF + m * 20 + kq;
    }
    // B slot: 1 x 16B per matrix per thread (16 rows x 16 chunks)
    int bk  = tid >> 4;
    int bnq = (tid & 15) << 2;
    const float* b1src = W1 + (size_t)bk * HH + n0 + bnq;
    const float* b3src = W3 + (size_t)bk * HH + n0 + bnq;
    int b1off = B1_OFF + bk * 72 + bnq;
    int b3off = B3_OFF + bk * 72 + bnq;

    uint32_t sbase = (uint32_t)__cvta_generic_to_shared(smemw);

    // prologue: prefetch tiles 0 and 1 (each its own commit group)
#pragma unroll
    for (int p = 0; p < 2; p++) {
        uint32_t sb = sbase + p * STG1_BYTES;
        int k0 = p * 16;
        cp16(sb + aoff[0] * 4, arow[0] + k0, asz[0]);
        cp16(sb + aoff[1] * 4, arow[1] + k0, asz[1]);
        cp16(sb + b1off * 4, b1src + (size_t)k0 * HH, 16);
        cp16(sb + b3off * 4, b3src + (size_t)k0 * HH, 16);
        cp_commit();
    }

    const int KB = DD / 16;
    for (int kb = 0; kb < KB; kb++) {
        // prefetch tile kb+2 (empty commit at tail keeps group indices aligned)
        if (kb + 2 < KB) {
            uint32_t sb = sbase + ((kb + 2) & 3) * STG1_BYTES;
            int k0 = (kb + 2) * 16;
            cp16(sb + aoff[0] * 4, arow[0] + k0, asz[0]);
            cp16(sb + aoff[1] * 4, arow[1] + k0, asz[1]);
            cp16(sb + b1off * 4, b1src + (size_t)k0 * HH, 16);
            cp16(sb + b3off * 4, b3src + (size_t)k0 * HH, 16);
        }
        cp_commit();
        cp_wait2();                         // tile kb landed

        uint32_t* stg = smemw + (kb & 3) * STG1_WORDS;

        // producer-side tf32 conversion of OWN chunks (no barrier needed first)
        cvt4(stg + aoff[0]);
        cvt4(stg + aoff[1]);
        cvt4(stg + b1off);
        cvt4(stg + b3off);
        __syncthreads();                    // publish converted tile kb

        const uint32_t* A_  = stg + A_OFF;
        const uint32_t* B1_ = stg + B1_OFF;
        const uint32_t* B3_ = stg + B3_OFF;

#pragma unroll
        for (int ks = 0; ks < 2; ks++) {
            int kk = ks * 8;
            uint32_t a[2][4];
#pragma unroll
            for (int mi = 0; mi < 2; mi++) {
                int mr = wm * 32 + mi * 16 + t8;
                a[mi][0] = A_[mr * 20 + kk + t4];
                a[mi][1] = A_[(mr + 8) * 20 + kk + t4];
                a[mi][2] = A_[mr * 20 + kk + t4 + 4];
                a[mi][3] = A_[(mr + 8) * 20 + kk + t4 + 4];
            }
            uint32_t b1r[4][2], b3r[4][2];
#pragma unroll
            for (int nj = 0; nj < 4; nj++) {
                int nc = wn * 32 + nj * 8 + t8;
                b1r[nj][0] = B1_[(kk + t4) * 72 + nc];
                b1r[nj][1] = B1_[(kk + t4 + 4) * 72 + nc];
                b3r[nj][0] = B3_[(kk + t4) * 72 + nc];
                b3r[nj][1] = B3_[(kk + t4 + 4) * 72 + nc];
            }
#pragma unroll
            for (int mi = 0; mi < 2; mi++)
#pragma unroll
                for (int nj = 0; nj < 4; nj++) {
                    mma8(accG[mi][nj], a[mi], b1r[nj]);
                    mma8(accU[mi][nj], a[mi], b3r[nj]);
                }
        }
        // no trailing barrier: 4-stage ring + distance-2 prefetch means the
        // buffer consumed here is only overwritten after next iter's barrier.
    }

    // epilogue: silu(G) * U -> g_hidden
#pragma unroll
    for (int mi = 0; mi < 2; mi++) {
#pragma unroll
        for (int h = 0; h < 2; h++) {
            int row = wm * 32 + mi * 16 + t8 + h * 8;
            int grow = bm0 + row;
            if (grow < M) {
                size_t base = (size_t)(rowbase + grow) * HH + n0;
#pragma unroll
                for (int nj = 0; nj < 4; nj++) {
                    int col = wn * 32 + nj * 8 + t4 * 2;
                    float2 st;
                    st.x = silu_f(accG[mi][nj][h * 2 + 0]) * accU[mi][nj][h * 2 + 0];
                    st.y = silu_f(accG[mi][nj][h * 2 + 1]) * accU[mi][nj][h * 2 + 1];
                    *reinterpret_cast<float2*>(&g_hidden[base + col]) = st;
                }
            }
        }
    }
}

// ---------------------------------------------------------------------------
// K4: grouped GEMM2: y = hidden @ W2  (moe -> g_y, shared -> out directly)
// grid (64, DD/128, 9), block 256. Tile 128x128. Same 4-stage ring.
// ---------------------------------------------------------------------------
#define B2_OFF   A_WORDS
#define B2_WORDS (16 * 136)                // stride 136 (136%32==8 -> conflict-free)
#define STG2_WORDS (A_WORDS + B2_WORDS)    // 4736
#define STG2_BYTES (STG2_WORDS * 4)        // 18944
#define SMEM2_BYTES (4 * STG2_BYTES)       // 75776

__global__ __launch_bounds__(256, 2)
void gemm2_kernel(const float* __restrict__ w2, const float* __restrict__ sw2,
                  float* __restrict__ out) {
    extern __shared__ uint32_t smemw[];

    int g = blockIdx.z;
    int M, rowbase;
    const float* W;
    if (g < EE) {
        M = g_count[g]; rowbase = g_offs[g];
        W = w2 + (size_t)g * HH * DD;
    } else {
        M = TT; rowbase = NMOE; W = sw2;
    }
    int bm0 = blockIdx.x * 128;
    if (bm0 >= M) return;
    int n0 = blockIdx.y * 128;

    int tid  = threadIdx.x;
    int lane = tid & 31, wid = tid >> 5;
    int wm = wid & 3, wn = wid >> 2;       // warp tile 32 x 64
    int t4 = lane & 3, t8 = lane >> 2;

    float acc[2][8][4] = {};

    const float* arow[2];
    int asz[2], aoff[2];
#pragma unroll
    for (int i = 0; i < 2; i++) {
        int s = tid + i * 256;
        int m = s >> 2;
        int kq = (s & 3) << 2;
        int gm = bm0 + m;
        if (gm < M) {
            arow[i] = g_hidden + (size_t)(rowbase + gm) * HH + kq;
            asz[i] = 16;
        } else {
            arow[i] = g_hidden;
            asz[i] = 0;
        }
        aoff[i] = A_OFF + m * 20 + kq;
    }
    // B: 16 rows x 128 floats = 512 chunks of 16B -> 2 per thread
    const float* bsrc[2];
    int boff[2];
#pragma unroll
    for (int i = 0; i < 2; i++) {
        int s = tid + i * 256;
        int k = s >> 5;
        int nq = (s & 31) << 2;
        bsrc[i] = W + (size_t)k * DD + n0 + nq;
        boff[i] = B2_OFF + k * 136 + nq;
    }

    uint32_t sbase = (uint32_t)__cvta_generic_to_shared(smemw);

#pragma unroll
    for (int p = 0; p < 2; p++) {
        uint32_t sb = sbase + p * STG2_BYTES;
        int k0 = p * 16;
        cp16(sb + aoff[0] * 4, arow[0] + k0, asz[0]);
        cp16(sb + aoff[1] * 4, arow[1] + k0, asz[1]);
        cp16(sb + boff[0] * 4, bsrc[0] + (size_t)k0 * DD, 16);
        cp16(sb + boff[1] * 4, bsrc[1] + (size_t)k0 * DD, 16);
        cp_commit();
    }

    const int KB = HH / 16;
    for (int kb = 0; kb < KB; kb++) {
        if (kb + 2 < KB) {
            uint32_t sb = sbase + ((kb + 2) & 3) * STG2_BYTES;
            int k0 = (kb + 2) * 16;
            cp16(sb + aoff[0] * 4, arow[0] + k0, asz[0]);
            cp16(sb + aoff[1] * 4, arow[1] + k0, asz[1]);
            cp16(sb + boff[0] * 4, bsrc[0] + (size_t)k0 * DD, 16);
            cp16(sb + boff[1] * 4, bsrc[1] + (size_t)k0 * DD, 16);
        }
        cp_commit();
        cp_wait2();

        uint32_t* stg = smemw + (kb & 3) * STG2_WORDS;

        cvt4(stg + aoff[0]);
        cvt4(stg + aoff[1]);
        cvt4(stg + boff[0]);
        cvt4(stg + boff[1]);
        __syncthreads();

        const uint32_t* A_ = stg + A_OFF;
        const uint32_t* B_ = stg + B2_OFF;

#pragma unroll
        for (int ks = 0; ks < 2; ks++) {
            int kk = ks * 8;
            uint32_t a[2][4];
#pragma unroll
            for (int mi = 0; mi < 2; mi++) {
                int mr = wm * 32 + mi * 16 + t8;
                a[mi][0] = A_[mr * 20 + kk + t4];
                a[mi][1] = A_[(mr + 8) * 20 + kk + t4];
                a[mi][2] = A_[mr * 20 + kk + t4 + 4];
                a[mi][3] = A_[(mr + 8) * 20 + kk + t4 + 4];
            }
            uint32_t br[8][2];
#pragma unroll
            for (int nj = 0; nj < 8; nj++) {
                int nc = wn * 64 + nj * 8 + t8;
                br[nj][0] = B_[(kk + t4) * 136 + nc];
                br[nj][1] = B_[(kk + t4 + 4) * 136 + nc];
            }
#pragma unroll
            for (int mi = 0; mi < 2; mi++)
#pragma unroll
                for (int nj = 0; nj < 8; nj++)
                    mma8(acc[mi][nj], a[mi], br[nj]);
        }
    }

#pragma unroll
    for (int mi = 0; mi < 2; mi++) {
#pragma unroll
        for (int h = 0; h < 2; h++) {
            int row = wm * 32 + mi * 16 + t8 + h * 8;
            int grow = bm0 + row;
            if (grow < M) {
#pragma unroll
                for (int nj = 0; nj < 8; nj++) {
                    int col = wn * 64 + nj * 8 + t4 * 2;
                    float2 st;
                    st.x = acc[mi][nj][h * 2 + 0];
                    st.y = acc[mi][nj][h * 2 + 1];
                    if (g < EE) {
                        size_t base = (size_t)(rowbase + grow) * DD + n0;
                        *reinterpret_cast<float2*>(&g_y[base + col]) = st;
                    } else {
                        size_t base = (size_t)grow * DD + n0;   // grow == token id
                        *reinterpret_cast<float2*>(&out[base + col]) = st;
                    }
                }
            }
        }
    }
}

// ---------------------------------------------------------------------------
// K5: combine: out[t] += w0*y[r0] + w1*y[r1]   (deterministic, no atomics)
// ---------------------------------------------------------------------------
__global__ void combine_kernel(float* __restrict__ out) {
    int t = blockIdx.x;
    int e0 = g_asg_e[2 * t],     e1 = g_asg_e[2 * t + 1];
    int r0 = g_offs[e0] + g_asg_pos[2 * t];
    int r1 = g_offs[e1] + g_asg_pos[2 * t + 1];
    float w0 = g_asg_w[2 * t], w1 = g_asg_w[2 * t + 1];

    int c = threadIdx.x * 4;
    float4 o  = *reinterpret_cast<const float4*>(out + (size_t)t * DD + c);
    float4 y0 = *reinterpret_cast<const float4*>(g_y + (size_t)r0 * DD + c);
    float4 y1 = *reinterpret_cast<const float4*>(g_y + (size_t)r1 * DD + c);
    o.x += w0 * y0.x + w1 * y1.x;
    o.y += w0 * y0.y + w1 * y1.y;
    o.z += w0 * y0.z + w1 * y1.z;
    o.w += w0 * y0.w + w1 * y1.w;
    *reinterpret_cast<float4*>(out + (size_t)t * DD + c) = o;
}

// ---------------------------------------------------------------------------
// Launch
// ---------------------------------------------------------------------------
extern "C" void kernel_launch(void* const* d_in, const int* in_sizes, int n_in,
                              void* d_out, int out_size) {
    const float* x    = (const float*)d_in[0];
    const float* rw   = (const float*)d_in[1];
    const float* bias = (const float*)d_in[2];
    const float* w1   = (const float*)d_in[3];
    const float* w3   = (const float*)d_in[4];
    const float* w2   = (const float*)d_in[5];
    const float* sw1  = (const float*)d_in[6];
    const float* sw3  = (const float*)d_in[7];
    const float* sw2  = (const float*)d_in[8];
    float* out = (float*)d_out;

    // dynamic smem opt-in (>48KB); host-side attr set, not a graph node
    cudaFuncSetAttribute(gemm1_kernel, cudaFuncAttributeMaxDynamicSharedMemorySize, SMEM1_BYTES);
    cudaFuncSetAttribute(gemm2_kernel, cudaFuncAttributeMaxDynamicSharedMemorySize, SMEM2_BYTES);

    zero_counts_kernel<<<1, 32>>>();
    router_kernel<<<TT / 8, 256>>>(x, rw, bias);
    offsets_kernel<<<1, 32>>>();

    dim3 grid1(TT / 128, HH / 64, EE + 1);
    gemm1_kernel<<<grid1, 256, SMEM1_BYTES>>>(x, w1, w3, sw1, sw3);

    dim3 grid2(TT / 128, DD / 128, EE + 1);
    gemm2_kernel<<<grid2, 256, SMEM2_BYTES>>>(w2, sw2, out);

    combine_kernel<<<TT, 256>>>(out);
}

// round 9
// speedup vs baseline: 1.2645x; 1.2645x over previous
#include <cuda_runtime.h>
#include <math.h>
#include <stdint.h>

// Problem constants
#define DD   1024          // model dim
#define HH   2048          // expert hidden
#define EE   8             // experts
#define TT   8192          // tokens (B*L = 4*2048)
#define KTOP 2
#define NMOE (TT * KTOP)   // 16384 moe assignments
#define NROWS (NMOE + TT)  // 24576 total grouped rows (moe + shared)

#define XSZ   ((size_t)TT * DD)        //  8.4M
#define WSZ   ((size_t)EE * DD * HH)   // 16.8M per expert weight tensor
#define SWSZ  ((size_t)DD * HH)        //  2.1M per shared weight tensor

// ---------------------------------------------------------------------------
// Scratch (static __device__ globals: allocation-free per harness rules)
// ---------------------------------------------------------------------------
__device__ float    g_hidden[(size_t)NROWS * HH];   // tf32-rounded bit patterns (as float)
__device__ float    g_y[(size_t)NMOE * DD];
__device__ uint32_t g_xtf[XSZ];                     // pre-converted tf32 bits
__device__ uint32_t g_w1tf[WSZ];
__device__ uint32_t g_w3tf[WSZ];
__device__ uint32_t g_w2tf[WSZ];
__device__ uint32_t g_sw1tf[SWSZ];
__device__ uint32_t g_sw3tf[SWSZ];
__device__ uint32_t g_sw2tf[SWSZ];
__device__ int   g_count[EE];
__device__ int   g_offs[EE + 1];
__device__ int   g_tok[EE * TT];
__device__ int   g_asg_e[NMOE];
__device__ int   g_asg_pos[NMOE];
__device__ float g_asg_w[NMOE];

// ---------------------------------------------------------------------------
// Helpers
// ---------------------------------------------------------------------------
__device__ __forceinline__ uint32_t f2tf(float f) {
    uint32_t r;
    asm("cvt.rna.tf32.f32 %0, %1;" : "=r"(r) : "f"(f));
    return r;
}

__device__ __forceinline__ void mma8(float c[4], const uint32_t a[4], const uint32_t b[2]) {
    asm volatile(
        "mma.sync.aligned.m16n8k8.row.col.f32.tf32.tf32.f32 "
        "{%0,%1,%2,%3},{%4,%5,%6,%7},{%8,%9},{%0,%1,%2,%3};\n"
        : "+f"(c[0]), "+f"(c[1]), "+f"(c[2]), "+f"(c[3])
        : "r"(a[0]), "r"(a[1]), "r"(a[2]), "r"(a[3]), "r"(b[0]), "r"(b[1]));
}

__device__ __forceinline__ void cp16(uint32_t smem_dst, const void* gmem_src, int src_size) {
    asm volatile("cp.async.ca.shared.global [%0], [%1], 16, %2;"
                 :: "r"(smem_dst), "l"(gmem_src), "r"(src_size));
}
__device__ __forceinline__ void cp_commit() { asm volatile("cp.async.commit_group;"); }
__device__ __forceinline__ void cp_wait2()  { asm volatile("cp.async.wait_group 2;" ::: "memory"); }

__device__ __forceinline__ float silu_f(float v) {
    return v / (1.0f + __expf(-v));
}

// ---------------------------------------------------------------------------
// K-1: elementwise tf32 pre-conversion (vectorized, grid-stride)
// ---------------------------------------------------------------------------
__global__ void cvt_tf32_kernel(const float4* __restrict__ src,
                                uint4* __restrict__ dst, int n4) {
    int i = blockIdx.x * blockDim.x + threadIdx.x;
    int stride = gridDim.x * blockDim.x;
    for (; i < n4; i += stride) {
        float4 v = src[i];
        uint4 o;
        o.x = f2tf(v.x); o.y = f2tf(v.y); o.z = f2tf(v.z); o.w = f2tf(v.w);
        dst[i] = o;
    }
}

// ---------------------------------------------------------------------------
// K0: zero counts (fresh every graph replay)
// ---------------------------------------------------------------------------
__global__ void zero_counts_kernel() {
    if (threadIdx.x < EE) g_count[threadIdx.x] = 0;
}

// ---------------------------------------------------------------------------
// K1: router
// ---------------------------------------------------------------------------
__global__ void router_kernel(const float* __restrict__ x,
                              const float* __restrict__ rw,
                              const float* __restrict__ bias) {
    int warp = threadIdx.x >> 5;
    int lane = threadIdx.x & 31;
    int t = blockIdx.x * 8 + warp;

    const float* xr = x + (size_t)t * DD;
    float xv[32];
#pragma unroll
    for (int i = 0; i < 32; i++) xv[i] = xr[lane + (i << 5)];

    float logit[EE];
#pragma unroll
    for (int e = 0; e < EE; e++) {
        const float* we = rw + e * DD;
        float acc = 0.0f;
#pragma unroll
        for (int i = 0; i < 32; i++) acc += xv[i] * we[lane + (i << 5)];
#pragma unroll
        for (int o = 16; o > 0; o >>= 1) acc += __shfl_xor_sync(0xffffffffu, acc, o);
        logit[e] = acc + bias[e];
    }

    if (lane == 0) {
        int e0 = 0;
#pragma unroll
        for (int e = 1; e < EE; e++) if (logit[e] > logit[e0]) e0 = e;
        int e1 = -1;
#pragma unroll
        for (int e = 0; e < EE; e++) {
            if (e == e0) continue;
            if (e1 < 0 || logit[e] > logit[e1]) e1 = e;
        }
        float l0 = logit[e0], l1 = logit[e1];
        float p1 = expf(l1 - l0);
        float inv = 1.0f / (1.0f + p1);
        float w0 = inv, w1 = p1 * inv;

        int pos0 = atomicAdd(&g_count[e0], 1);
        int pos1 = atomicAdd(&g_count[e1], 1);
        g_tok[e0 * TT + pos0] = t;
        g_tok[e1 * TT + pos1] = t;
        g_asg_e[2 * t]     = e0; g_asg_pos[2 * t]     = pos0; g_asg_w[2 * t]     = w0;
        g_asg_e[2 * t + 1] = e1; g_asg_pos[2 * t + 1] = pos1; g_asg_w[2 * t + 1] = w1;
    }
}

// ---------------------------------------------------------------------------
// K2: prefix offsets
// ---------------------------------------------------------------------------
__global__ void offsets_kernel() {
    if (threadIdx.x == 0 && blockIdx.x == 0) {
        int a = 0;
        for (int e = 0; e < EE; e++) { g_offs[e] = a; a += g_count[e]; }
        g_offs[EE] = a;
    }
}

// ---------------------------------------------------------------------------
// K3: grouped GEMM1 (dual): hidden = silu(X W1) * (X W3), gathered rows.
// All operands pre-converted tf32 bits. 4-stage cp.async ring, distance-2
// prefetch, ONE __syncthreads per K-tile, zero in-loop conversions.
// ---------------------------------------------------------------------------
#define A_OFF   0
#define A_WORDS (128 * 20)                 // stride 20, conflict-free
#define B1_OFF  A_WORDS
#define B1_WORDS (16 * 72)                 // stride 72, conflict-free
#define B3_OFF  (B1_OFF + B1_WORDS)
#define STG1_WORDS (A_WORDS + 2 * B1_WORDS)
#define STG1_BYTES (STG1_WORDS * 4)
#define SMEM1_BYTES (4 * STG1_BYTES)       // 77824

__global__ __launch_bounds__(256, 2)
void gemm1_kernel() {
    extern __shared__ uint32_t smemw[];

    int g = blockIdx.z;
    int M, rowbase;
    const int* toks;
    const uint32_t *W1, *W3;
    if (g < EE) {
        M = g_count[g]; rowbase = g_offs[g]; toks = g_tok + g * TT;
        W1 = g_w1tf + (size_t)g * DD * HH; W3 = g_w3tf + (size_t)g * DD * HH;
    } else {
        M = TT; rowbase = NMOE; toks = nullptr;
        W1 = g_sw1tf; W3 = g_sw3tf;
    }
    int bm0 = blockIdx.x * 128;
    if (bm0 >= M) return;
    int n0 = blockIdx.y * 64;

    int tid  = threadIdx.x;
    int lane = tid & 31, wid = tid >> 5;
    int wm = wid & 3, wn = wid >> 2;       // 4x2 warps -> 32x32 per warp
    int t4 = lane & 3, t8 = lane >> 2;

    float accG[2][4][4] = {}, accU[2][4][4] = {};

    // A slots: 2 x 16B per thread (128 rows x 4 chunks)
    const uint32_t* arow[2];
    int asz[2], aoff[2];
#pragma unroll
    for (int i = 0; i < 2; i++) {
        int s = tid + i * 256;
        int m = s >> 2;
        int kq = (s & 3) << 2;
        int gm = bm0 + m;
        if (gm < M) {
            int tr = toks ? toks[gm] : gm;
            arow[i] = g_xtf + (size_t)tr * DD + kq;
            asz[i] = 16;
        } else {
            arow[i] = g_xtf;
            asz[i] = 0;
        }
        aoff[i] = A_OFF + m * 20 + kq;
    }
    // B slot: 1 x 16B per matrix per thread
    int bk  = tid >> 4;
    int bnq = (tid & 15) << 2;
    const uint32_t* b1src = W1 + (size_t)bk * HH + n0 + bnq;
    const uint32_t* b3src = W3 + (size_t)bk * HH + n0 + bnq;
    int b1off = B1_OFF + bk * 72 + bnq;
    int b3off = B3_OFF + bk * 72 + bnq;

    uint32_t sbase = (uint32_t)__cvta_generic_to_shared(smemw);

    // prologue: prefetch tiles 0 and 1
#pragma unroll
    for (int p = 0; p < 2; p++) {
        uint32_t sb = sbase + p * STG1_BYTES;
        int k0 = p * 16;
        cp16(sb + aoff[0] * 4, arow[0] + k0, asz[0]);
        cp16(sb + aoff[1] * 4, arow[1] + k0, asz[1]);
        cp16(sb + b1off * 4, b1src + (size_t)k0 * HH, 16);
        cp16(sb + b3off * 4, b3src + (size_t)k0 * HH, 16);
        cp_commit();
    }

    const int KB = DD / 16;
    for (int kb = 0; kb < KB; kb++) {
        if (kb + 2 < KB) {
            uint32_t sb = sbase + ((kb + 2) & 3) * STG1_BYTES;
            int k0 = (kb + 2) * 16;
            cp16(sb + aoff[0] * 4, arow[0] + k0, asz[0]);
            cp16(sb + aoff[1] * 4, arow[1] + k0, asz[1]);
            cp16(sb + b1off * 4, b1src + (size_t)k0 * HH, 16);
            cp16(sb + b3off * 4, b3src + (size_t)k0 * HH, 16);
        }
        cp_commit();
        cp_wait2();                          // tile kb landed
        __syncthreads();                     // publish tile kb / protect ring

        const uint32_t* stg = smemw + (kb & 3) * STG1_WORDS;
        const uint32_t* A_  = stg + A_OFF;
        const uint32_t* B1_ = stg + B1_OFF;
        const uint32_t* B3_ = stg + B3_OFF;

#pragma unroll
        for (int ks = 0; ks < 2; ks++) {
            int kk = ks * 8;
            uint32_t a[2][4];
#pragma unroll
            for (int mi = 0; mi < 2; mi++) {
                int mr = wm * 32 + mi * 16 + t8;
                a[mi][0] = A_[mr * 20 + kk + t4];
                a[mi][1] = A_[(mr + 8) * 20 + kk + t4];
                a[mi][2] = A_[mr * 20 + kk + t4 + 4];
                a[mi][3] = A_[(mr + 8) * 20 + kk + t4 + 4];
            }
            uint32_t b1r[4][2], b3r[4][2];
#pragma unroll
            for (int nj = 0; nj < 4; nj++) {
                int nc = wn * 32 + nj * 8 + t8;
                b1r[nj][0] = B1_[(kk + t4) * 72 + nc];
                b1r[nj][1] = B1_[(kk + t4 + 4) * 72 + nc];
                b3r[nj][0] = B3_[(kk + t4) * 72 + nc];
                b3r[nj][1] = B3_[(kk + t4 + 4) * 72 + nc];
            }
#pragma unroll
            for (int mi = 0; mi < 2; mi++)
#pragma unroll
                for (int nj = 0; nj < 4; nj++) {
                    mma8(accG[mi][nj], a[mi], b1r[nj]);
                    mma8(accU[mi][nj], a[mi], b3r[nj]);
                }
        }
    }

    // epilogue: silu(G) * U, rounded to tf32 bits -> g_hidden (feeds gemm2 raw)
#pragma unroll
    for (int mi = 0; mi < 2; mi++) {
#pragma unroll
        for (int h = 0; h < 2; h++) {
            int row = wm * 32 + mi * 16 + t8 + h * 8;
            int grow = bm0 + row;
            if (grow < M) {
                size_t base = (size_t)(rowbase + grow) * HH + n0;
#pragma unroll
                for (int nj = 0; nj < 4; nj++) {
                    int col = wn * 32 + nj * 8 + t4 * 2;
                    float2 st;
                    st.x = __uint_as_float(f2tf(
                        silu_f(accG[mi][nj][h * 2 + 0]) * accU[mi][nj][h * 2 + 0]));
                    st.y = __uint_as_float(f2tf(
                        silu_f(accG[mi][nj][h * 2 + 1]) * accU[mi][nj][h * 2 + 1]));
                    *reinterpret_cast<float2*>(&g_hidden[base + col]) = st;
                }
            }
        }
    }
}

// ---------------------------------------------------------------------------
// K4: grouped GEMM2: y = hidden @ W2. Tile 128x128. Same pipeline, no cvt.
// ---------------------------------------------------------------------------
#define B2_OFF   A_WORDS
#define B2_WORDS (16 * 136)
#define STG2_WORDS (A_WORDS + B2_WORDS)
#define STG2_BYTES (STG2_WORDS * 4)
#define SMEM2_BYTES (4 * STG2_BYTES)       // 75776

__global__ __launch_bounds__(256, 2)
void gemm2_kernel(float* __restrict__ out) {
    extern __shared__ uint32_t smemw[];

    int g = blockIdx.z;
    int M, rowbase;
    const uint32_t* W;
    if (g < EE) {
        M = g_count[g]; rowbase = g_offs[g];
        W = g_w2tf + (size_t)g * HH * DD;
    } else {
        M = TT; rowbase = NMOE; W = g_sw2tf;
    }
    int bm0 = blockIdx.x * 128;
    if (bm0 >= M) return;
    int n0 = blockIdx.y * 128;

    int tid  = threadIdx.x;
    int lane = tid & 31, wid = tid >> 5;
    int wm = wid & 3, wn = wid >> 2;       // warp tile 32 x 64
    int t4 = lane & 3, t8 = lane >> 2;

    float acc[2][8][4] = {};

    const float* arow[2];
    int asz[2], aoff[2];
#pragma unroll
    for (int i = 0; i < 2; i++) {
        int s = tid + i * 256;
        int m = s >> 2;
        int kq = (s & 3) << 2;
        int gm = bm0 + m;
        if (gm < M) {
            arow[i] = g_hidden + (size_t)(rowbase + gm) * HH + kq;
            asz[i] = 16;
        } else {
            arow[i] = g_hidden;
            asz[i] = 0;
        }
        aoff[i] = A_OFF + m * 20 + kq;
    }
    const uint32_t* bsrc[2];
    int boff[2];
#pragma unroll
    for (int i = 0; i < 2; i++) {
        int s = tid + i * 256;
        int k = s >> 5;
        int nq = (s & 31) << 2;
        bsrc[i] = W + (size_t)k * DD + n0 + nq;
        boff[i] = B2_OFF + k * 136 + nq;
    }

    uint32_t sbase = (uint32_t)__cvta_generic_to_shared(smemw);

#pragma unroll
    for (int p = 0; p < 2; p++) {
        uint32_t sb = sbase + p * STG2_BYTES;
        int k0 = p * 16;
        cp16(sb + aoff[0] * 4, arow[0] + k0, asz[0]);
        cp16(sb + aoff[1] * 4, arow[1] + k0, asz[1]);
        cp16(sb + boff[0] * 4, bsrc[0] + (size_t)k0 * DD, 16);
        cp16(sb + boff[1] * 4, bsrc[1] + (size_t)k0 * DD, 16);
        cp_commit();
    }

    const int KB = HH / 16;
    for (int kb = 0; kb < KB; kb++) {
        if (kb + 2 < KB) {
            uint32_t sb = sbase + ((kb + 2) & 3) * STG2_BYTES;
            int k0 = (kb + 2) * 16;
            cp16(sb + aoff[0] * 4, arow[0] + k0, asz[0]);
            cp16(sb + aoff[1] * 4, arow[1] + k0, asz[1]);
            cp16(sb + boff[0] * 4, bsrc[0] + (size_t)k0 * DD, 16);
            cp16(sb + boff[1] * 4, bsrc[1] + (size_t)k0 * DD, 16);
        }
        cp_commit();
        cp_wait2();
        __syncthreads();

        const uint32_t* stg = smemw + (kb & 3) * STG2_WORDS;
        const uint32_t* A_ = stg + A_OFF;
        const uint32_t* B_ = stg + B2_OFF;

#pragma unroll
        for (int ks = 0; ks < 2; ks++) {
            int kk = ks * 8;
            uint32_t a[2][4];
#pragma unroll
            for (int mi = 0; mi < 2; mi++) {
                int mr = wm * 32 + mi * 16 + t8;
                a[mi][0] = A_[mr * 20 + kk + t4];
                a[mi][1] = A_[(mr + 8) * 20 + kk + t4];
                a[mi][2] = A_[mr * 20 + kk + t4 + 4];
                a[mi][3] = A_[(mr + 8) * 20 + kk + t4 + 4];
            }
            uint32_t br[8][2];
#pragma unroll
            for (int nj = 0; nj < 8; nj++) {
                int nc = wn * 64 + nj * 8 + t8;
                br[nj][0] = B_[(kk + t4) * 136 + nc];
                br[nj][1] = B_[(kk + t4 + 4) * 136 + nc];
            }
#pragma unroll
            for (int mi = 0; mi < 2; mi++)
#pragma unroll
                for (int nj = 0; nj < 8; nj++)
                    mma8(acc[mi][nj], a[mi], br[nj]);
        }
    }

#pragma unroll
    for (int mi = 0; mi < 2; mi++) {
#pragma unroll
        for (int h = 0; h < 2; h++) {
            int row = wm * 32 + mi * 16 + t8 + h * 8;
            int grow = bm0 + row;
            if (grow < M) {
#pragma unroll
                for (int nj = 0; nj < 8; nj++) {
                    int col = wn * 64 + nj * 8 + t4 * 2;
                    float2 st;
                    st.x = acc[mi][nj][h * 2 + 0];
                    st.y = acc[mi][nj][h * 2 + 1];
                    if (g < EE) {
                        size_t base = (size_t)(rowbase + grow) * DD + n0;
                        *reinterpret_cast<float2*>(&g_y[base + col]) = st;
                    } else {
                        size_t base = (size_t)grow * DD + n0;   // grow == token id
                        *reinterpret_cast<float2*>(&out[base + col]) = st;
                    }
                }
            }
        }
    }
}

// ---------------------------------------------------------------------------
// K5: combine: out[t] += w0*y[r0] + w1*y[r1]
// ---------------------------------------------------------------------------
__global__ void combine_kernel(float* __restrict__ out) {
    int t = blockIdx.x;
    int e0 = g_asg_e[2 * t],     e1 = g_asg_e[2 * t + 1];
    int r0 = g_offs[e0] + g_asg_pos[2 * t];
    int r1 = g_offs[e1] + g_asg_pos[2 * t + 1];
    float w0 = g_asg_w[2 * t], w1 = g_asg_w[2 * t + 1];

    int c = threadIdx.x * 4;
    float4 o  = *reinterpret_cast<const float4*>(out + (size_t)t * DD + c);
    float4 y0 = *reinterpret_cast<const float4*>(g_y + (size_t)r0 * DD + c);
    float4 y1 = *reinterpret_cast<const float4*>(g_y + (size_t)r1 * DD + c);
    o.x += w0 * y0.x + w1 * y1.x;
    o.y += w0 * y0.y + w1 * y1.y;
    o.z += w0 * y0.z + w1 * y1.z;
    o.w += w0 * y0.w + w1 * y1.w;
    *reinterpret_cast<float4*>(out + (size_t)t * DD + c) = o;
}

// ---------------------------------------------------------------------------
// Launch
// ---------------------------------------------------------------------------
extern "C" void kernel_launch(void* const* d_in, const int* in_sizes, int n_in,
                              void* d_out, int out_size) {
    const float* x    = (const float*)d_in[0];
    const float* rw   = (const float*)d_in[1];
    const float* bias = (const float*)d_in[2];
    const float* w1   = (const float*)d_in[3];
    const float* w3   = (const float*)d_in[4];
    const float* w2   = (const float*)d_in[5];
    const float* sw1  = (const float*)d_in[6];
    const float* sw3  = (const float*)d_in[7];
    const float* sw2  = (const float*)d_in[8];
    float* out = (float*)d_out;

    cudaFuncSetAttribute(gemm1_kernel, cudaFuncAttributeMaxDynamicSharedMemorySize, SMEM1_BYTES);
    cudaFuncSetAttribute(gemm2_kernel, cudaFuncAttributeMaxDynamicSharedMemorySize, SMEM2_BYTES);

    uint32_t* xtf;   cudaGetSymbolAddress((void**)&xtf,  g_xtf);
    uint32_t* w1tf;  cudaGetSymbolAddress((void**)&w1tf, g_w1tf);
    uint32_t* w3tf;  cudaGetSymbolAddress((void**)&w3tf, g_w3tf);
    uint32_t* w2tf;  cudaGetSymbolAddress((void**)&w2tf, g_w2tf);
    uint32_t* s1tf;  cudaGetSymbolAddress((void**)&s1tf, g_sw1tf);
    uint32_t* s3tf;  cudaGetSymbolAddress((void**)&s3tf, g_sw3tf);
    uint32_t* s2tf;  cudaGetSymbolAddress((void**)&s2tf, g_sw2tf);

    // pre-convert everything to tf32 bits (grid-stride, 1792 blocks x 256)
    cvt_tf32_kernel<<<1792, 256>>>((const float4*)x,   (uint4*)xtf,  (int)(XSZ  / 4));
    cvt_tf32_kernel<<<1792, 256>>>((const float4*)w1,  (uint4*)w1tf, (int)(WSZ  / 4));
    cvt_tf32_kernel<<<1792, 256>>>((const float4*)w3,  (uint4*)w3tf, (int)(WSZ  / 4));
    cvt_tf32_kernel<<<1792, 256>>>((const float4*)w2,  (uint4*)w2tf, (int)(WSZ  / 4));
    cvt_tf32_kernel<<<1792, 256>>>((const float4*)sw1, (uint4*)s1tf, (int)(SWSZ / 4));
    cvt_tf32_kernel<<<1792, 256>>>((const float4*)sw3, (uint4*)s3tf, (int)(SWSZ / 4));
    cvt_tf32_kernel<<<1792, 256>>>((const float4*)sw2, (uint4*)s2tf, (int)(SWSZ / 4));

    zero_counts_kernel<<<1, 32>>>();
    router_kernel<<<TT / 8, 256>>>(x, rw, bias);
    offsets_kernel<<<1, 32>>>();

    dim3 grid1(TT / 128, HH / 64, EE + 1);
    gemm1_kernel<<<grid1, 256, SMEM1_BYTES>>>();

    dim3 grid2(TT / 128, DD / 128, EE + 1);
    gemm2_kernel<<<grid2, 256, SMEM2_BYTES>>>(out);

    combine_kernel<<<TT, 256>>>(out);
}

// round 10
// speedup vs baseline: 1.2762x; 1.0093x over previous
#include <cuda_runtime.h>
#include <math.h>
#include <stdint.h>

// Problem constants
#define DD   1024          // model dim
#define HH   2048          // expert hidden
#define EE   8             // experts
#define TT   8192          // tokens (B*L = 4*2048)
#define KTOP 2
#define NMOE (TT * KTOP)   // 16384 moe assignments
#define NROWS (NMOE + TT)  // 24576 total grouped rows (moe + shared)

#define XSZ   ((size_t)TT * DD)
#define WSZ   ((size_t)EE * DD * HH)
#define SWSZ  ((size_t)DD * HH)

// ---------------------------------------------------------------------------
// Scratch (static __device__ globals: allocation-free per harness rules)
// ---------------------------------------------------------------------------
__device__ float    g_hidden[(size_t)NROWS * HH];   // tf32-rounded bits (as float)
__device__ float    g_y[(size_t)NMOE * DD];
__device__ uint32_t g_xtf[XSZ];                     // pre-converted tf32 bits
__device__ uint32_t g_w1tf[WSZ];
__device__ uint32_t g_w3tf[WSZ];
__device__ uint32_t g_w2tf[WSZ];
__device__ uint32_t g_sw1tf[SWSZ];
__device__ uint32_t g_sw3tf[SWSZ];
__device__ uint32_t g_sw2tf[SWSZ];
__device__ int   g_count[EE];
__device__ int   g_offs[EE + 1];
__device__ int   g_tok[EE * TT];
__device__ int   g_asg_e[NMOE];
__device__ int   g_asg_pos[NMOE];
__device__ float g_asg_w[NMOE];

// ---------------------------------------------------------------------------
// Helpers
// ---------------------------------------------------------------------------
__device__ __forceinline__ uint32_t f2tf(float f) {
    uint32_t r;
    asm("cvt.rna.tf32.f32 %0, %1;" : "=r"(r) : "f"(f));
    return r;
}

__device__ __forceinline__ void mma8(float c[4], const uint32_t a[4], const uint32_t b[2]) {
    asm volatile(
        "mma.sync.aligned.m16n8k8.row.col.f32.tf32.tf32.f32 "
        "{%0,%1,%2,%3},{%4,%5,%6,%7},{%8,%9},{%0,%1,%2,%3};\n"
        : "+f"(c[0]), "+f"(c[1]), "+f"(c[2]), "+f"(c[3])
        : "r"(a[0]), "r"(a[1]), "r"(a[2]), "r"(a[3]), "r"(b[0]), "r"(b[1]));
}

__device__ __forceinline__ void cp16(uint32_t smem_dst, const void* gmem_src, int src_size) {
    asm volatile("cp.async.ca.shared.global [%0], [%1], 16, %2;"
                 :: "r"(smem_dst), "l"(gmem_src), "r"(src_size));
}
__device__ __forceinline__ void cp_commit() { asm volatile("cp.async.commit_group;"); }
__device__ __forceinline__ void cp_wait2()  { asm volatile("cp.async.wait_group 2;" ::: "memory"); }

__device__ __forceinline__ float silu_f(float v) {
    return v / (1.0f + __expf(-v));
}

// B-tile XOR swizzle: element (k, n) -> word k*STRIDE + (n ^ (8*(k&3)))
// Consumer reads (k = kk+t4, n = base + t8): bank = 8*((c ^ t4)&3) + t8 -> 32 distinct.
// 16B cp.async chunks (n0 % 4 == 0) stay inside one 8-word group (XOR flips bits 3-4).
__device__ __forceinline__ int bswz(int k, int n) {
    return (n ^ ((k & 3) << 3));
}

// ---------------------------------------------------------------------------
// K-1: elementwise tf32 pre-conversion (vectorized, grid-stride)
// ---------------------------------------------------------------------------
__global__ void cvt_tf32_kernel(const float4* __restrict__ src,
                                uint4* __restrict__ dst, int n4) {
    int i = blockIdx.x * blockDim.x + threadIdx.x;
    int stride = gridDim.x * blockDim.x;
    for (; i < n4; i += stride) {
        float4 v = src[i];
        uint4 o;
        o.x = f2tf(v.x); o.y = f2tf(v.y); o.z = f2tf(v.z); o.w = f2tf(v.w);
        dst[i] = o;
    }
}

// ---------------------------------------------------------------------------
// K0: zero counts
// ---------------------------------------------------------------------------
__global__ void zero_counts_kernel() {
    if (threadIdx.x < EE) g_count[threadIdx.x] = 0;
}

// ---------------------------------------------------------------------------
// K1: router
// ---------------------------------------------------------------------------
__global__ void router_kernel(const float* __restrict__ x,
                              const float* __restrict__ rw,
                              const float* __restrict__ bias) {
    int warp = threadIdx.x >> 5;
    int lane = threadIdx.x & 31;
    int t = blockIdx.x * 8 + warp;

    const float* xr = x + (size_t)t * DD;
    float xv[32];
#pragma unroll
    for (int i = 0; i < 32; i++) xv[i] = xr[lane + (i << 5)];

    float logit[EE];
#pragma unroll
    for (int e = 0; e < EE; e++) {
        const float* we = rw + e * DD;
        float acc = 0.0f;
#pragma unroll
        for (int i = 0; i < 32; i++) acc += xv[i] * we[lane + (i << 5)];
#pragma unroll
        for (int o = 16; o > 0; o >>= 1) acc += __shfl_xor_sync(0xffffffffu, acc, o);
        logit[e] = acc + bias[e];
    }

    if (lane == 0) {
        int e0 = 0;
#pragma unroll
        for (int e = 1; e < EE; e++) if (logit[e] > logit[e0]) e0 = e;
        int e1 = -1;
#pragma unroll
        for (int e = 0; e < EE; e++) {
            if (e == e0) continue;
            if (e1 < 0 || logit[e] > logit[e1]) e1 = e;
        }
        float l0 = logit[e0], l1 = logit[e1];
        float p1 = expf(l1 - l0);
        float inv = 1.0f / (1.0f + p1);
        float w0 = inv, w1 = p1 * inv;

        int pos0 = atomicAdd(&g_count[e0], 1);
        int pos1 = atomicAdd(&g_count[e1], 1);
        g_tok[e0 * TT + pos0] = t;
        g_tok[e1 * TT + pos1] = t;
        g_asg_e[2 * t]     = e0; g_asg_pos[2 * t]     = pos0; g_asg_w[2 * t]     = w0;
        g_asg_e[2 * t + 1] = e1; g_asg_pos[2 * t + 1] = pos1; g_asg_w[2 * t + 1] = w1;
    }
}

// ---------------------------------------------------------------------------
// K2: prefix offsets
// ---------------------------------------------------------------------------
__global__ void offsets_kernel() {
    if (threadIdx.x == 0 && blockIdx.x == 0) {
        int a = 0;
        for (int e = 0; e < EE; e++) { g_offs[e] = a; a += g_count[e]; }
        g_offs[EE] = a;
    }
}

// ---------------------------------------------------------------------------
// K3: grouped GEMM1 (dual): hidden = silu(X W1) * (X W3), gathered rows.
// 4-stage cp.async ring, distance-2 prefetch, 1 barrier/K-tile,
// XOR-swizzled B (conflict-free fragment reads), pre-converted operands.
// ---------------------------------------------------------------------------
#define A_OFF   0
#define A_WORDS (128 * 20)                 // A stride 20: conflict-free column reads
#define B1_OFF  A_WORDS
#define B1_WORDS (16 * 64)                 // stride 64, XOR swizzle
#define B3_OFF  (B1_OFF + B1_WORDS)
#define STG1_WORDS (A_WORDS + 2 * B1_WORDS)   // 4608
#define STG1_BYTES (STG1_WORDS * 4)           // 18432
#define SMEM1_BYTES (4 * STG1_BYTES)          // 73728

__global__ __launch_bounds__(256, 2)
void gemm1_kernel() {
    extern __shared__ uint32_t smemw[];

    int g = blockIdx.z;
    int M, rowbase;
    const int* toks;
    const uint32_t *W1, *W3;
    if (g < EE) {
        M = g_count[g]; rowbase = g_offs[g]; toks = g_tok + g * TT;
        W1 = g_w1tf + (size_t)g * DD * HH; W3 = g_w3tf + (size_t)g * DD * HH;
    } else {
        M = TT; rowbase = NMOE; toks = nullptr;
        W1 = g_sw1tf; W3 = g_sw3tf;
    }
    int bm0 = blockIdx.x * 128;
    if (bm0 >= M) return;
    int n0 = blockIdx.y * 64;

    int tid  = threadIdx.x;
    int lane = tid & 31, wid = tid >> 5;
    int wm = wid & 3, wn = wid >> 2;       // 4x2 warps -> 32x32 per warp
    int t4 = lane & 3, t8 = lane >> 2;

    float accG[2][4][4] = {}, accU[2][4][4] = {};

    // A slots: 2 x 16B per thread (128 rows x 4 chunks)
    const uint32_t* arow[2];
    int asz[2], aoff[2];
#pragma unroll
    for (int i = 0; i < 2; i++) {
        int s = tid + i * 256;
        int m = s >> 2;
        int kq = (s & 3) << 2;
        int gm = bm0 + m;
        if (gm < M) {
            int tr = toks ? toks[gm] : gm;
            arow[i] = g_xtf + (size_t)tr * DD + kq;
            asz[i] = 16;
        } else {
            arow[i] = g_xtf;
            asz[i] = 0;
        }
        aoff[i] = A_OFF + m * 20 + kq;
    }
    // B slot: 1 x 16B per matrix per thread (16 rows x 16 chunks) -> swizzled dst
    int bk  = tid >> 4;
    int bnq = (tid & 15) << 2;
    const uint32_t* b1src = W1 + (size_t)bk * HH + n0 + bnq;
    const uint32_t* b3src = W3 + (size_t)bk * HH + n0 + bnq;
    int b1off = B1_OFF + bk * 64 + bswz(bk, bnq);
    int b3off = B3_OFF + bk * 64 + bswz(bk, bnq);

    uint32_t sbase = (uint32_t)__cvta_generic_to_shared(smemw);

    // prologue: prefetch tiles 0 and 1
#pragma unroll
    for (int p = 0; p < 2; p++) {
        uint32_t sb = sbase + p * STG1_BYTES;
        int k0 = p * 16;
        cp16(sb + aoff[0] * 4, arow[0] + k0, asz[0]);
        cp16(sb + aoff[1] * 4, arow[1] + k0, asz[1]);
        cp16(sb + b1off * 4, b1src + (size_t)k0 * HH, 16);
        cp16(sb + b3off * 4, b3src + (size_t)k0 * HH, 16);
        cp_commit();
    }

    const int KB = DD / 16;
    for (int kb = 0; kb < KB; kb++) {
        if (kb + 2 < KB) {
            uint32_t sb = sbase + ((kb + 2) & 3) * STG1_BYTES;
            int k0 = (kb + 2) * 16;
            cp16(sb + aoff[0] * 4, arow[0] + k0, asz[0]);
            cp16(sb + aoff[1] * 4, arow[1] + k0, asz[1]);
            cp16(sb + b1off * 4, b1src + (size_t)k0 * HH, 16);
            cp16(sb + b3off * 4, b3src + (size_t)k0 * HH, 16);
        }
        cp_commit();
        cp_wait2();
        __syncthreads();

        const uint32_t* stg = smemw + (kb & 3) * STG1_WORDS;
        const uint32_t* A_  = stg + A_OFF;
        const uint32_t* B1_ = stg + B1_OFF;
        const uint32_t* B3_ = stg + B3_OFF;

        // per-thread swizzled column index (XOR depends only on t4 within a k-group)
        int sx = t4 << 3;

#pragma unroll
        for (int ks = 0; ks < 2; ks++) {
            int kk = ks * 8;
            uint32_t a[2][4];
#pragma unroll
            for (int mi = 0; mi < 2; mi++) {
                int mr = wm * 32 + mi * 16 + t8;
                a[mi][0] = A_[mr * 20 + kk + t4];
                a[mi][1] = A_[(mr + 8) * 20 + kk + t4];
                a[mi][2] = A_[mr * 20 + kk + t4 + 4];
                a[mi][3] = A_[(mr + 8) * 20 + kk + t4 + 4];
            }
            uint32_t b1r[4][2], b3r[4][2];
            int r0 = (kk + t4) * 64;
            int r1 = (kk + t4 + 4) * 64;
#pragma unroll
            for (int nj = 0; nj < 4; nj++) {
                int nc = (wn * 32 + nj * 8 + t8) ^ sx;   // swizzled read
                b1r[nj][0] = B1_[r0 + nc];
                b1r[nj][1] = B1_[r1 + nc];
                b3r[nj][0] = B3_[r0 + nc];
                b3r[nj][1] = B3_[r1 + nc];
            }
#pragma unroll
            for (int mi = 0; mi < 2; mi++)
#pragma unroll
                for (int nj = 0; nj < 4; nj++) {
                    mma8(accG[mi][nj], a[mi], b1r[nj]);
                    mma8(accU[mi][nj], a[mi], b3r[nj]);
                }
        }
    }

    // epilogue: silu(G) * U, rounded to tf32 bits -> g_hidden (feeds gemm2 raw)
#pragma unroll
    for (int mi = 0; mi < 2; mi++) {
#pragma unroll
        for (int h = 0; h < 2; h++) {
            int row = wm * 32 + mi * 16 + t8 + h * 8;
            int grow = bm0 + row;
            if (grow < M) {
                size_t base = (size_t)(rowbase + grow) * HH + n0;
#pragma unroll
                for (int nj = 0; nj < 4; nj++) {
                    int col = wn * 32 + nj * 8 + t4 * 2;
                    float2 st;
                    st.x = __uint_as_float(f2tf(
                        silu_f(accG[mi][nj][h * 2 + 0]) * accU[mi][nj][h * 2 + 0]));
                    st.y = __uint_as_float(f2tf(
                        silu_f(accG[mi][nj][h * 2 + 1]) * accU[mi][nj][h * 2 + 1]));
                    *reinterpret_cast<float2*>(&g_hidden[base + col]) = st;
                }
            }
        }
    }
}

// ---------------------------------------------------------------------------
// K4: grouped GEMM2: y = hidden @ W2. Tile 128x128, swizzled B.
// ---------------------------------------------------------------------------
#define B2_OFF   A_WORDS
#define B2_WORDS (16 * 128)                // stride 128, XOR swizzle
#define STG2_WORDS (A_WORDS + B2_WORDS)    // 4608
#define STG2_BYTES (STG2_WORDS * 4)        // 18432
#define SMEM2_BYTES (4 * STG2_BYTES)       // 73728

__global__ __launch_bounds__(256, 2)
void gemm2_kernel(float* __restrict__ out) {
    extern __shared__ uint32_t smemw[];

    int g = blockIdx.z;
    int M, rowbase;
    const uint32_t* W;
    if (g < EE) {
        M = g_count[g]; rowbase = g_offs[g];
        W = g_w2tf + (size_t)g * HH * DD;
    } else {
        M = TT; rowbase = NMOE; W = g_sw2tf;
    }
    int bm0 = blockIdx.x * 128;
    if (bm0 >= M) return;
    int n0 = blockIdx.y * 128;

    int tid  = threadIdx.x;
    int lane = tid & 31, wid = tid >> 5;
    int wm = wid & 3, wn = wid >> 2;       // warp tile 32 x 64
    int t4 = lane & 3, t8 = lane >> 2;

    float acc[2][8][4] = {};

    const float* arow[2];
    int asz[2], aoff[2];
#pragma unroll
    for (int i = 0; i < 2; i++) {
        int s = tid + i * 256;
        int m = s >> 2;
        int kq = (s & 3) << 2;
        int gm = bm0 + m;
        if (gm < M) {
            arow[i] = g_hidden + (size_t)(rowbase + gm) * HH + kq;
            asz[i] = 16;
        } else {
            arow[i] = g_hidden;
            asz[i] = 0;
        }
        aoff[i] = A_OFF + m * 20 + kq;
    }
    const uint32_t* bsrc[2];
    int boff[2];
#pragma unroll
    for (int i = 0; i < 2; i++) {
        int s = tid + i * 256;
        int k = s >> 5;
        int nq = (s & 31) << 2;
        bsrc[i] = W + (size_t)k * DD + n0 + nq;
        boff[i] = B2_OFF + k * 128 + bswz(k, nq);
    }

    uint32_t sbase = (uint32_t)__cvta_generic_to_shared(smemw);

#pragma unroll
    for (int p = 0; p < 2; p++) {
        uint32_t sb = sbase + p * STG2_BYTES;
        int k0 = p * 16;
        cp16(sb + aoff[0] * 4, arow[0] + k0, asz[0]);
        cp16(sb + aoff[1] * 4, arow[1] + k0, asz[1]);
        cp16(sb + boff[0] * 4, bsrc[0] + (size_t)k0 * DD, 16);
        cp16(sb + boff[1] * 4, bsrc[1] + (size_t)k0 * DD, 16);
        cp_commit();
    }

    const int KB = HH / 16;
    for (int kb = 0; kb < KB; kb++) {
        if (kb + 2 < KB) {
            uint32_t sb = sbase + ((kb + 2) & 3) * STG2_BYTES;
            int k0 = (kb + 2) * 16;
            cp16(sb + aoff[0] * 4, arow[0] + k0, asz[0]);
            cp16(sb + aoff[1] * 4, arow[1] + k0, asz[1]);
            cp16(sb + boff[0] * 4, bsrc[0] + (size_t)k0 * DD, 16);
            cp16(sb + boff[1] * 4, bsrc[1] + (size_t)k0 * DD, 16);
        }
        cp_commit();
        cp_wait2();
        __syncthreads();

        const uint32_t* stg = smemw + (kb & 3) * STG2_WORDS;
        const uint32_t* A_ = stg + A_OFF;
        const uint32_t* B_ = stg + B2_OFF;

        int sx = t4 << 3;

#pragma unroll
        for (int ks = 0; ks < 2; ks++) {
            int kk = ks * 8;
            uint32_t a[2][4];
#pragma unroll
            for (int mi = 0; mi < 2; mi++) {
                int mr = wm * 32 + mi * 16 + t8;
                a[mi][0] = A_[mr * 20 + kk + t4];
                a[mi][1] = A_[(mr + 8) * 20 + kk + t4];
                a[mi][2] = A_[mr * 20 + kk + t4 + 4];
                a[mi][3] = A_[(mr + 8) * 20 + kk + t4 + 4];
            }
            uint32_t br[8][2];
            int r0 = (kk + t4) * 128;
            int r1 = (kk + t4 + 4) * 128;
#pragma unroll
            for (int nj = 0; nj < 8; nj++) {
                int nc = (wn * 64 + nj * 8 + t8) ^ sx;   // swizzled read
                br[nj][0] = B_[r0 + nc];
                br[nj][1] = B_[r1 + nc];
            }
#pragma unroll
            for (int mi = 0; mi < 2; mi++)
#pragma unroll
                for (int nj = 0; nj < 8; nj++)
                    mma8(acc[mi][nj], a[mi], br[nj]);
        }
    }

#pragma unroll
    for (int mi = 0; mi < 2; mi++) {
#pragma unroll
        for (int h = 0; h < 2; h++) {
            int row = wm * 32 + mi * 16 + t8 + h * 8;
            int grow = bm0 + row;
            if (grow < M) {
#pragma unroll
                for (int nj = 0; nj < 8; nj++) {
                    int col = wn * 64 + nj * 8 + t4 * 2;
                    float2 st;
                    st.x = acc[mi][nj][h * 2 + 0];
                    st.y = acc[mi][nj][h * 2 + 1];
                    if (g < EE) {
                        size_t base = (size_t)(rowbase + grow) * DD + n0;
                        *reinterpret_cast<float2*>(&g_y[base + col]) = st;
                    } else {
                        size_t base = (size_t)grow * DD + n0;   // grow == token id
                        *reinterpret_cast<float2*>(&out[base + col]) = st;
                    }
                }
            }
        }
    }
}

// ---------------------------------------------------------------------------
// K5: combine: out[t] += w0*y[r0] + w1*y[r1]
// ---------------------------------------------------------------------------
__global__ void combine_kernel(float* __restrict__ out) {
    int t = blockIdx.x;
    int e0 = g_asg_e[2 * t],     e1 = g_asg_e[2 * t + 1];
    int r0 = g_offs[e0] + g_asg_pos[2 * t];
    int r1 = g_offs[e1] + g_asg_pos[2 * t + 1];
    float w0 = g_asg_w[2 * t], w1 = g_asg_w[2 * t + 1];

    int c = threadIdx.x * 4;
    float4 o  = *reinterpret_cast<const float4*>(out + (size_t)t * DD + c);
    float4 y0 = *reinterpret_cast<const float4*>(g_y + (size_t)r0 * DD + c);
    float4 y1 = *reinterpret_cast<const float4*>(g_y + (size_t)r1 * DD + c);
    o.x += w0 * y0.x + w1 * y1.x;
    o.y += w0 * y0.y + w1 * y1.y;
    o.z += w0 * y0.z + w1 * y1.z;
    o.w += w0 * y0.w + w1 * y1.w;
    *reinterpret_cast<float4*>(out + (size_t)t * DD + c) = o;
}

// ---------------------------------------------------------------------------
// Launch
// ---------------------------------------------------------------------------
extern "C" void kernel_launch(void* const* d_in, const int* in_sizes, int n_in,
                              void* d_out, int out_size) {
    const float* x    = (const float*)d_in[0];
    const float* rw   = (const float*)d_in[1];
    const float* bias = (const float*)d_in[2];
    const float* w1   = (const float*)d_in[3];
    const float* w3   = (const float*)d_in[4];
    const float* w2   = (const float*)d_in[5];
    const float* sw1  = (const float*)d_in[6];
    const float* sw3  = (const float*)d_in[7];
    const float* sw2  = (const float*)d_in[8];
    float* out = (float*)d_out;

    cudaFuncSetAttribute(gemm1_kernel, cudaFuncAttributeMaxDynamicSharedMemorySize, SMEM1_BYTES);
    cudaFuncSetAttribute(gemm2_kernel, cudaFuncAttributeMaxDynamicSharedMemorySize, SMEM2_BYTES);

    uint32_t* xtf;   cudaGetSymbolAddress((void**)&xtf,  g_xtf);
    uint32_t* w1tf;  cudaGetSymbolAddress((void**)&w1tf, g_w1tf);
    uint32_t* w3tf;  cudaGetSymbolAddress((void**)&w3tf, g_w3tf);
    uint32_t* w2tf;  cudaGetSymbolAddress((void**)&w2tf, g_w2tf);
    uint32_t* s1tf;  cudaGetSymbolAddress((void**)&s1tf, g_sw1tf);
    uint32_t* s3tf;  cudaGetSymbolAddress((void**)&s3tf, g_sw3tf);
    uint32_t* s2tf;  cudaGetSymbolAddress((void**)&s2tf, g_sw2tf);

    // pre-convert everything to tf32 bits
    cvt_tf32_kernel<<<1792, 256>>>((const float4*)x,   (uint4*)xtf,  (int)(XSZ  / 4));
    cvt_tf32_kernel<<<1792, 256>>>((const float4*)w1,  (uint4*)w1tf, (int)(WSZ  / 4));
    cvt_tf32_kernel<<<1792, 256>>>((const float4*)w3,  (uint4*)w3tf, (int)(WSZ  / 4));
    cvt_tf32_kernel<<<1792, 256>>>((const float4*)w2,  (uint4*)w2tf, (int)(WSZ  / 4));
    cvt_tf32_kernel<<<1792, 256>>>((const float4*)sw1, (uint4*)s1tf, (int)(SWSZ / 4));
    cvt_tf32_kernel<<<1792, 256>>>((const float4*)sw3, (uint4*)s3tf, (int)(SWSZ / 4));
    cvt_tf32_kernel<<<1792, 256>>>((const float4*)sw2, (uint4*)s2tf, (int)(SWSZ / 4));

    zero_counts_kernel<<<1, 32>>>();
    router_kernel<<<TT / 8, 256>>>(x, rw, bias);
    offsets_kernel<<<1, 32>>>();

    dim3 grid1(TT / 128, HH / 64, EE + 1);
    gemm1_kernel<<<grid1, 256, SMEM1_BYTES>>>();

    dim3 grid2(TT / 128, DD / 128, EE + 1);
    gemm2_kernel<<<grid2, 256, SMEM2_BYTES>>>(out);

    combine_kernel<<<TT, 256>>>(out);
}